// round 3
// baseline (speedup 1.0000x reference)
#include <cuda_runtime.h>
#include <cstdint>
#include <cstddef>

// Problem constants
#define NN 32768
#define KK 8192
#define DD 64

// Output layout (tuple order, flattened):
//   encodings  [N,K]   @ 0
//   codebook   [K,D]   @ OFF_CB
//   cluster_sz [K]     @ OFF_CS
//   ema_w_new  [K,D]   @ OFF_EMA
//   embed_new  [K,D]   @ OFF_EMB
#define OFF_CB  268435456ULL
#define OFF_CS  268959744ULL
#define OFF_EMA 268967936ULL
#define OFF_EMB 269492224ULL

#define DECAY 0.99f
#define OMD   0.01f      // f32(1.0 - 0.99) == f32(0.01) bitwise
#define EPSV  1e-5f
#define KEPS  0.08192f   // K * EPS

// Scratch (device globals; no allocations allowed)
__device__ int   g_idx[NN];
__device__ float g_e2[KK];
__device__ float g_cnt[KK];
__device__ float g_dw[KK * DD];
__device__ float g_n;

// ---------------------------------------------------------------------------
// 0) zero scratch (graph replays must start clean)
// ---------------------------------------------------------------------------
__global__ void zero_scratch_kernel() {
    int i = blockIdx.x * 256 + threadIdx.x;
    if (i < KK * DD) g_dw[i] = 0.0f;
    if (i < KK)      g_cnt[i] = 0.0f;
}

// ---------------------------------------------------------------------------
// 1) codebook squared norms
// ---------------------------------------------------------------------------
__global__ void e2_kernel(const float* __restrict__ e) {
    int k = blockIdx.x * 256 + threadIdx.x;   // K threads
    const float4* p = reinterpret_cast<const float4*>(e + (size_t)k * DD);
    float s = 0.0f;
#pragma unroll
    for (int i = 0; i < 16; ++i) {
        float4 v = p[i];
        s += v.x * v.x + v.y * v.y + v.z * v.z + v.w * v.w;
    }
    g_e2[k] = s;
}

// ---------------------------------------------------------------------------
// 2) argmin kernel: 128 rows x 128 codewords per CTA, 8x8 micro-tile
//    dist = e2[k] - 2 * dot(x, e_k)   (||x||^2 dropped: row-constant)
// ---------------------------------------------------------------------------
#define XPAD 132   // 128 rows + 4 pad: 16B-aligned rows, conflict-free LDS128

__global__ __launch_bounds__(256, 2)
void argmin_kernel(const float* __restrict__ x, const float* __restrict__ e) {
    extern __shared__ float sm[];
    float* xs = sm;                 // [DD][XPAD] : x transposed, resident
    float* es = sm + DD * XPAD;     // [DD][XPAD] : e tile, streamed

    const int tid = threadIdx.x;
    const int tx = tid & 15;        // column group (8 codewords)
    const int ty = tid >> 4;        // row group (8 rows)
    const int row0 = blockIdx.x * 128;

    // Stage x tile once (transposed: [d][row])
    {
        const float4* xg = reinterpret_cast<const float4*>(x + (size_t)row0 * DD);
#pragma unroll
        for (int i = tid; i < 2048; i += 256) {
            int r = i >> 4, d4 = i & 15;
            float4 v = xg[(size_t)r * 16 + d4];
            xs[(d4 * 4 + 0) * XPAD + r] = v.x;
            xs[(d4 * 4 + 1) * XPAD + r] = v.y;
            xs[(d4 * 4 + 2) * XPAD + r] = v.z;
            xs[(d4 * 4 + 3) * XPAD + r] = v.w;
        }
    }

    float best[8];
    int   bidx[8];
#pragma unroll
    for (int r = 0; r < 8; ++r) { best[r] = 3.402823466e38f; bidx[r] = 0; }

    for (int k0 = 0; k0 < KK; k0 += 128) {
        __syncthreads();   // protect es from previous iteration's readers
        {
            const float4* eg = reinterpret_cast<const float4*>(e + (size_t)k0 * DD);
#pragma unroll
            for (int i = tid; i < 2048; i += 256) {
                int r = i >> 4, d4 = i & 15;
                float4 v = eg[(size_t)r * 16 + d4];
                es[(d4 * 4 + 0) * XPAD + r] = v.x;
                es[(d4 * 4 + 1) * XPAD + r] = v.y;
                es[(d4 * 4 + 2) * XPAD + r] = v.z;
                es[(d4 * 4 + 3) * XPAD + r] = v.w;
            }
        }
        __syncthreads();

        float acc[8][8];
#pragma unroll
        for (int r = 0; r < 8; ++r)
#pragma unroll
            for (int c = 0; c < 8; ++c) acc[r][c] = 0.0f;

#pragma unroll 8
        for (int d = 0; d < DD; ++d) {
            float4 xa = *reinterpret_cast<const float4*>(&xs[d * XPAD + ty * 8]);
            float4 xb = *reinterpret_cast<const float4*>(&xs[d * XPAD + ty * 8 + 4]);
            float4 ea = *reinterpret_cast<const float4*>(&es[d * XPAD + tx * 8]);
            float4 eb = *reinterpret_cast<const float4*>(&es[d * XPAD + tx * 8 + 4]);
            float xr[8] = {xa.x, xa.y, xa.z, xa.w, xb.x, xb.y, xb.z, xb.w};
            float er[8] = {ea.x, ea.y, ea.z, ea.w, eb.x, eb.y, eb.z, eb.w};
#pragma unroll
            for (int r = 0; r < 8; ++r)
#pragma unroll
                for (int c = 0; c < 8; ++c)
                    acc[r][c] = fmaf(xr[r], er[c], acc[r][c]);
        }

        // distances for this tile + running min (first-index tie-break: scan order
        // within thread is ascending k; strict < keeps the earliest)
        float4 p = *reinterpret_cast<const float4*>(&g_e2[k0 + tx * 8]);
        float4 q = *reinterpret_cast<const float4*>(&g_e2[k0 + tx * 8 + 4]);
        float e2r[8] = {p.x, p.y, p.z, p.w, q.x, q.y, q.z, q.w};
#pragma unroll
        for (int c = 0; c < 8; ++c) {
            int kk = k0 + tx * 8 + c;
#pragma unroll
            for (int r = 0; r < 8; ++r) {
                float dist = fmaf(-2.0f, acc[r][c], e2r[c]);
                if (dist < best[r]) { best[r] = dist; bidx[r] = kk; }
            }
        }
    }

    // Reduce across the 16 tx lanes (lanes differ in low 4 bits of lane id).
    // Tie-break to the smaller codeword index (matches jnp.argmin first-min).
#pragma unroll
    for (int m = 8; m > 0; m >>= 1) {
#pragma unroll
        for (int r = 0; r < 8; ++r) {
            float ob = __shfl_xor_sync(0xffffffffu, best[r], m);
            int   oi = __shfl_xor_sync(0xffffffffu, bidx[r], m);
            if (ob < best[r] || (ob == best[r] && oi < bidx[r])) {
                best[r] = ob; bidx[r] = oi;
            }
        }
    }
    if (tx == 0) {
#pragma unroll
        for (int r = 0; r < 8; ++r)
            g_idx[row0 + ty * 8 + r] = bidx[r];
    }
}

// ---------------------------------------------------------------------------
// 3) encodings: fused zero + one-hot, float4 stores (write-bound, ~1.07 GB)
// ---------------------------------------------------------------------------
__global__ void onehot_kernel(float4* __restrict__ out) {
    int i = blockIdx.x * 256 + threadIdx.x;     // 67,108,864 float4s
    int row = i >> 11;                          // K/4 = 2048 float4 per row
    int c4  = i & 2047;
    int idx = __ldg(&g_idx[row]);
    float4 v = make_float4(0.0f, 0.0f, 0.0f, 0.0f);
    if ((idx >> 2) == c4) {
        reinterpret_cast<float*>(&v)[idx & 3] = 1.0f;
    }
    out[i] = v;
}

// ---------------------------------------------------------------------------
// 4) dw scatter + counts.  Count atomics are exact integers in fp32 ->
//    bit-deterministic; dw fp32 atomics vary at ulp level only (tolerated).
// ---------------------------------------------------------------------------
__global__ void scatter_kernel(const float* __restrict__ x) {
    int gid = blockIdx.x * 256 + threadIdx.x;   // N*D = 2,097,152
    int n = gid >> 6, d = gid & 63;
    int k = g_idx[n];
    atomicAdd(&g_dw[(size_t)k * DD + d], x[gid]);
    if (d == 0) atomicAdd(&g_cnt[k], 1.0f);
}

// ---------------------------------------------------------------------------
// 5) n = sum(cluster_size_pre)
// ---------------------------------------------------------------------------
__global__ void reduce_n_kernel(const float* __restrict__ ema_cs) {
    __shared__ float sh[1024];
    int t = threadIdx.x;
    float s = 0.0f;
    for (int k = t; k < KK; k += 1024) {
        float cs = __fadd_rn(__fmul_rn(ema_cs[k], DECAY), __fmul_rn(OMD, g_cnt[k]));
        s += cs;
    }
    sh[t] = s;
    __syncthreads();
    for (int m = 512; m > 0; m >>= 1) {
        if (t < m) sh[t] += sh[t + m];
        __syncthreads();
    }
    if (t == 0) g_n = sh[0];
}

// ---------------------------------------------------------------------------
// 6) finalize: codebook copy, normalized cluster size, EMA weights, embedding
//    (explicit __fmul_rn/__fadd_rn to prevent FMA contraction and match the
//    reference's separate mul/add rounding)
// ---------------------------------------------------------------------------
__global__ void finalize_kernel(const float* __restrict__ emb_w,
                                const float* __restrict__ ema_w,
                                const float* __restrict__ ema_cs,
                                float* __restrict__ out) {
    int gid = blockIdx.x * 256 + threadIdx.x;   // K*D = 524,288
    int k = gid >> 6, d = gid & 63;
    float nsum = g_n;
    float cs  = __fadd_rn(__fmul_rn(ema_cs[k], DECAY), __fmul_rn(OMD, g_cnt[k]));
    float csn = __fmul_rn(__fdiv_rn(__fadd_rn(cs, EPSV), __fadd_rn(nsum, KEPS)), nsum);
    float ema_new = __fadd_rn(__fmul_rn(ema_w[gid], DECAY), __fmul_rn(OMD, g_dw[gid]));
    out[OFF_CB  + gid] = emb_w[gid];
    out[OFF_EMA + gid] = ema_new;
    out[OFF_EMB + gid] = __fdiv_rn(ema_new, csn);
    if (d == 0) out[OFF_CS + k] = csn;
}

// ---------------------------------------------------------------------------
extern "C" void kernel_launch(void* const* d_in, const int* in_sizes, int n_in,
                              void* d_out, int out_size) {
    const float* x       = (const float*)d_in[0];   // inputs          [N,D]
    const float* emb_w   = (const float*)d_in[1];   // embedding_w     [K,D]
    const float* ema_w   = (const float*)d_in[2];   // ema_w           [K,D]
    const float* ema_cs  = (const float*)d_in[3];   // ema_cluster_sz  [K]
    float* out = (float*)d_out;

    // Function attributes persist process-wide; setting every call is harmless
    // and guarantees it's in effect before the first (non-capture) launch.
    cudaFuncSetAttribute(argmin_kernel,
                         cudaFuncAttributeMaxDynamicSharedMemorySize,
                         2 * DD * XPAD * (int)sizeof(float));

    zero_scratch_kernel<<<2048, 256>>>();
    e2_kernel<<<KK / 256, 256>>>(emb_w);
    argmin_kernel<<<NN / 128, 256, 2 * DD * XPAD * (int)sizeof(float)>>>(x, emb_w);
    onehot_kernel<<<(NN * (KK / 4)) / 256, 256>>>((float4*)out);
    scatter_kernel<<<(NN * DD) / 256, 256>>>(x);
    reduce_n_kernel<<<1, 1024>>>(ema_cs);
    finalize_kernel<<<(KK * DD) / 256, 256>>>(emb_w, ema_w, ema_cs, out);
}

// round 5
// speedup vs baseline: 1.2302x; 1.2302x over previous
#include <cuda_runtime.h>
#include <cstdint>
#include <cstddef>

// Problem constants
#define NN 32768
#define KK 8192
#define DD 64

// Output layout (tuple order, flattened)
#define OFF_CB  268435456ULL
#define OFF_CS  268959744ULL
#define OFF_EMA 268967936ULL
#define OFF_EMB 269492224ULL

#define DECAY 0.99f
#define OMD   0.01f
#define EPSV  1e-5f
#define KEPS  0.08192f   // K * EPS

// Scratch (device globals; no allocations allowed)
__device__ int   g_idx[NN];
__device__ float g_e2[KK];
__device__ float g_cnt[KK];
__device__ float g_dw[KK * DD];
__device__ float g_n;

// ===========================================================================
// helpers (sm_80-era PTX only: safe for a plain sm_103 ptxas target)
// ===========================================================================
static __device__ __forceinline__ uint32_t smem_u32(const void* p) {
    uint32_t a;
    asm("{ .reg .u64 t; cvta.to.shared.u64 t, %1; cvt.u32.u64 %0, t; }"
        : "=r"(a) : "l"(p));
    return a;
}

#define CP_ASYNC16(dst, src) \
    asm volatile("cp.async.cg.shared.global [%0], [%1], 16;" \
                 :: "r"(dst), "l"(src) : "memory")
#define CP_COMMIT() asm volatile("cp.async.commit_group;" ::: "memory")
#define CP_WAIT0()  asm volatile("cp.async.wait_group 0;"  ::: "memory")

// m16n8k8 row.col tf32 MMA, D += A*B (C aliases D)
static __device__ __forceinline__ void mma_tf32(float* d, const uint32_t* a,
                                                const uint32_t* b) {
    asm volatile(
        "mma.sync.aligned.m16n8k8.row.col.f32.tf32.tf32.f32 "
        "{%0,%1,%2,%3}, {%4,%5,%6,%7}, {%8,%9}, {%0,%1,%2,%3};"
        : "+f"(d[0]), "+f"(d[1]), "+f"(d[2]), "+f"(d[3])
        : "r"(a[0]), "r"(a[1]), "r"(a[2]), "r"(a[3]), "r"(b[0]), "r"(b[1]));
}

static __device__ __forceinline__ uint32_t to_tf32(float v) {
    uint32_t r;
    asm("cvt.rna.tf32.f32 %0, %1;" : "=r"(r) : "f"(v));
    return r;
}

// ===========================================================================
// 0) zero scratch
// ===========================================================================
__global__ void zero_scratch_kernel() {
    int i = blockIdx.x * 256 + threadIdx.x;
    if (i < KK * DD) g_dw[i] = 0.0f;
    if (i < KK)      g_cnt[i] = 0.0f;
}

// ===========================================================================
// 1) codebook squared norms
// ===========================================================================
__global__ void e2_kernel(const float* __restrict__ e) {
    int k = blockIdx.x * 256 + threadIdx.x;
    const float4* p = reinterpret_cast<const float4*>(e + (size_t)k * DD);
    float s = 0.0f;
#pragma unroll
    for (int i = 0; i < 16; ++i) {
        float4 v = p[i];
        s += v.x * v.x + v.y * v.y + v.z * v.z + v.w * v.w;
    }
    g_e2[k] = s;
}

// ===========================================================================
// 2) Tensor-core argmin via mma.sync (HMMA tf32), 3-term split precision.
//    CTA = 256 threads = 8 warps laid out 4(m) x 2(n).
//    Per CTA: 128 rows; loop over 64 codeword tiles of 128.
//    Warp tile: m=32 (2 mfrags), n=64 (8 nblocks), k=64 (8 ksteps).
//    A (x hi+lo tf32 fragments) persistent in registers.
//    B (raw f32 e-tile) double-buffered in SMEM via cp.async;
//    hi/lo split done in registers at fragment-load time.
// ===========================================================================
#define SP   68                       // smem row stride in floats (64 + 4 pad)
#define SPB  (SP * 4)                 // 272 bytes
#define EBUF (128 * SPB)              // 34816 bytes per e-tile buffer
#define CAND_OFF (2 * EBUF)           // candidate arrays after the 2 buffers
#define ARG_SMEM (CAND_OFF + 128 * 2 * 8)

__global__ __launch_bounds__(256, 1)
void argmin_mma_kernel(const float* __restrict__ x, const float* __restrict__ e) {
    extern __shared__ char sm[];
    const uint32_t sb = smem_u32(sm);
    const int tid = threadIdx.x;
    const int wid = tid >> 5;
    const int lane = tid & 31;
    const int g = lane >> 2;          // group id (0..7)
    const int r = lane & 3;           // thread-in-group (0..3)
    const int mw = wid & 3;           // m-warp (0..3) -> rows mw*32..+31
    const int nw = wid >> 2;          // n-warp (0..1) -> cols nw*64..+63
    const int row0 = blockIdx.x * 128;
    const int Cn = nw * 64;

    float* cand_d = reinterpret_cast<float*>(sm + CAND_OFF);
    int*   cand_i = reinterpret_cast<int*>(sm + CAND_OFF + 128 * 2 * 4);

    // ---- stage x tile (raw f32) into buffer 0: [row][dim], stride SP ----
    {
        const float4* xg = reinterpret_cast<const float4*>(x + (size_t)row0 * DD);
#pragma unroll
        for (int i = 0; i < 8; ++i) {
            int ch = tid + 256 * i;            // 0..2047 float4s
            int row = ch >> 4, q = ch & 15;
            *reinterpret_cast<float4*>(sm + row * SPB + q * 16) = xg[ch];
        }
    }
    __syncthreads();

    // ---- build persistent A fragments (hi & lo tf32) ----
    uint32_t ahi[2][8][4], alo[2][8][4];
#pragma unroll
    for (int mf = 0; mf < 2; ++mf) {
#pragma unroll
        for (int ks = 0; ks < 8; ++ks) {
#pragma unroll
            for (int j = 0; j < 4; ++j) {
                int row = mw * 32 + mf * 16 + g + ((j & 1) ? 8 : 0);
                int dim = ks * 8 + r + ((j & 2) ? 4 : 0);
                float v = *reinterpret_cast<const float*>(sm + row * SPB + dim * 4);
                uint32_t h = to_tf32(v);
                ahi[mf][ks][j] = h;
                alo[mf][ks][j] = to_tf32(v - __uint_as_float(h));
            }
        }
    }
    __syncthreads();   // everyone done reading buffer 0 before tile-0 cp.async

    // ---- preload e tile 0 into buffer 0 ----
    {
        const char* src = reinterpret_cast<const char*>(e);
#pragma unroll
        for (int i = 0; i < 8; ++i) {
            int ch = tid + 256 * i;
            int n = ch >> 4, kq = ch & 15;
            CP_ASYNC16(sb + n * SPB + kq * 16, src + ch * 16);
        }
    }
    CP_COMMIT();
    CP_WAIT0();
    __syncthreads();

    float best[4];
    int   bidx[4];
#pragma unroll
    for (int s = 0; s < 4; ++s) { best[s] = 3.402823466e38f; bidx[s] = 0; }

    const int NTILES = KK / 128;   // 64
    for (int t = 0; t < NTILES; ++t) {
        const uint32_t bufc = sb + (uint32_t)(t & 1) * EBUF;

        // prefetch tile t+1 into the other buffer
        if (t + 1 < NTILES) {
            const char* src = reinterpret_cast<const char*>(e + (size_t)(t + 1) * 128 * DD);
            const uint32_t bufn = sb + (uint32_t)((t + 1) & 1) * EBUF;
#pragma unroll
            for (int i = 0; i < 8; ++i) {
                int ch = tid + 256 * i;
                int n = ch >> 4, kq = ch & 15;
                CP_ASYNC16(bufn + n * SPB + kq * 16, src + ch * 16);
            }
        }
        CP_COMMIT();

        // ---- compute: D[2][8][4] over k=64, 3 tf32 terms ----
        float D[2][8][4];
#pragma unroll
        for (int mf = 0; mf < 2; ++mf)
#pragma unroll
            for (int nb = 0; nb < 8; ++nb)
#pragma unroll
                for (int j = 0; j < 4; ++j) D[mf][nb][j] = 0.0f;

#pragma unroll
        for (int nb = 0; nb < 8; ++nb) {
            const uint32_t nbase = bufc + (uint32_t)(Cn + nb * 8 + g) * SPB;
#pragma unroll
            for (int ks = 0; ks < 8; ++ks) {
                float v0 = *reinterpret_cast<const float*>(
                    (uintptr_t)(sm) + (nbase - sb) + (ks * 8 + r) * 4);
                float v1 = *reinterpret_cast<const float*>(
                    (uintptr_t)(sm) + (nbase - sb) + (ks * 8 + r + 4) * 4);
                uint32_t bhi[2], blo[2];
                bhi[0] = to_tf32(v0);
                bhi[1] = to_tf32(v1);
                blo[0] = to_tf32(v0 - __uint_as_float(bhi[0]));
                blo[1] = to_tf32(v1 - __uint_as_float(bhi[1]));
                mma_tf32(D[0][nb], ahi[0][ks], bhi);
                mma_tf32(D[1][nb], ahi[1][ks], bhi);
                mma_tf32(D[0][nb], alo[0][ks], bhi);
                mma_tf32(D[1][nb], alo[1][ks], bhi);
                mma_tf32(D[0][nb], ahi[0][ks], blo);
                mma_tf32(D[1][nb], ahi[1][ks], blo);
            }
        }

        // ---- epilogue: distances + running argmin ----
        // D frag c-layout: c0(row g, col 2r), c1(row g, col 2r+1),
        //                  c2(row g+8, col 2r), c3(row g+8, col 2r+1)
#pragma unroll
        for (int nb = 0; nb < 8; ++nb) {
            int col = t * 128 + Cn + nb * 8 + r * 2;
            float2 q = *reinterpret_cast<const float2*>(&g_e2[col]);
#pragma unroll
            for (int mf = 0; mf < 2; ++mf) {
                float d0 = fmaf(-2.0f, D[mf][nb][0], q.x);
                float d1 = fmaf(-2.0f, D[mf][nb][1], q.y);
                float d2 = fmaf(-2.0f, D[mf][nb][2], q.x);
                float d3 = fmaf(-2.0f, D[mf][nb][3], q.y);
                int s0 = mf * 2, s1 = mf * 2 + 1;
                if (d0 < best[s0]) { best[s0] = d0; bidx[s0] = col; }
                if (d1 < best[s0]) { best[s0] = d1; bidx[s0] = col + 1; }
                if (d2 < best[s1]) { best[s1] = d2; bidx[s1] = col; }
                if (d3 < best[s1]) { best[s1] = d3; bidx[s1] = col + 1; }
            }
        }

        CP_WAIT0();
        __syncthreads();
    }

    // ---- reduce across the 4 lanes of each quad (same rows, different cols)
#pragma unroll
    for (int m = 1; m <= 2; m <<= 1) {
#pragma unroll
        for (int s = 0; s < 4; ++s) {
            float ob = __shfl_xor_sync(0xffffffffu, best[s], m);
            int   oi = __shfl_xor_sync(0xffffffffu, bidx[s], m);
            if (ob < best[s] || (ob == best[s] && oi < bidx[s])) {
                best[s] = ob; bidx[s] = oi;
            }
        }
    }
    if (r == 0) {
        // rows owned: mw*32 + g + {0,8,16,24}
#pragma unroll
        for (int s = 0; s < 4; ++s) {
            int row = mw * 32 + g + s * 8;     // s: 0->+0,1->+8,2->+16,3->+24
            // slot order: s0 rows g, s1 rows g+8, s2 rows g+16, s3 rows g+24
            cand_d[nw * 128 + row] = best[s];
            cand_i[nw * 128 + row] = bidx[s];
        }
    }
    __syncthreads();
    if (tid < 128) {
        float d0 = cand_d[tid],       d1 = cand_d[128 + tid];
        int   i0 = cand_i[tid],       i1 = cand_i[128 + tid];
        int win = (d1 < d0 || (d1 == d0 && i1 < i0)) ? i1 : i0;
        g_idx[row0 + tid] = win;
    }
}

// ===========================================================================
// 3) encodings: fused zero + one-hot, 64B per thread, streaming stores
// ===========================================================================
__global__ void onehot_kernel(float4* __restrict__ out) {
    int gid = blockIdx.x * 256 + threadIdx.x;   // 16,777,216 threads
    int row = gid >> 9;                         // 512 x 16-float segments/row
    int seg = gid & 511;
    int idx = __ldg(&g_idx[row]);
    float4* p = out + (size_t)gid * 4;
    float4 z = make_float4(0.0f, 0.0f, 0.0f, 0.0f);
    if ((idx >> 4) != seg) {
        __stcs(p + 0, z); __stcs(p + 1, z); __stcs(p + 2, z); __stcs(p + 3, z);
    } else {
        float4 v[4] = {z, z, z, z};
        reinterpret_cast<float*>(v)[idx & 15] = 1.0f;
        __stcs(p + 0, v[0]); __stcs(p + 1, v[1]);
        __stcs(p + 2, v[2]); __stcs(p + 3, v[3]);
    }
}

// ===========================================================================
// 4) dw scatter + counts
// ===========================================================================
__global__ void scatter_kernel(const float* __restrict__ x) {
    int gid = blockIdx.x * 256 + threadIdx.x;
    int n = gid >> 6, d = gid & 63;
    int k = g_idx[n];
    atomicAdd(&g_dw[(size_t)k * DD + d], x[gid]);
    if (d == 0) atomicAdd(&g_cnt[k], 1.0f);
}

// ===========================================================================
// 5) n = sum(cluster_size_pre)
// ===========================================================================
__global__ void reduce_n_kernel(const float* __restrict__ ema_cs) {
    __shared__ float sh[1024];
    int t = threadIdx.x;
    float s = 0.0f;
    for (int k = t; k < KK; k += 1024) {
        float cs = __fadd_rn(__fmul_rn(ema_cs[k], DECAY), __fmul_rn(OMD, g_cnt[k]));
        s += cs;
    }
    sh[t] = s;
    __syncthreads();
    for (int m = 512; m > 0; m >>= 1) {
        if (t < m) sh[t] += sh[t + m];
        __syncthreads();
    }
    if (t == 0) g_n = sh[0];
}

// ===========================================================================
// 6) finalize
// ===========================================================================
__global__ void finalize_kernel(const float* __restrict__ emb_w,
                                const float* __restrict__ ema_w,
                                const float* __restrict__ ema_cs,
                                float* __restrict__ out) {
    int gid = blockIdx.x * 256 + threadIdx.x;
    int k = gid >> 6, d = gid & 63;
    float nsum = g_n;
    float cs  = __fadd_rn(__fmul_rn(ema_cs[k], DECAY), __fmul_rn(OMD, g_cnt[k]));
    float csn = __fmul_rn(__fdiv_rn(__fadd_rn(cs, EPSV), __fadd_rn(nsum, KEPS)), nsum);
    float ema_new = __fadd_rn(__fmul_rn(ema_w[gid], DECAY), __fmul_rn(OMD, g_dw[gid]));
    out[OFF_CB  + gid] = emb_w[gid];
    out[OFF_EMA + gid] = ema_new;
    out[OFF_EMB + gid] = __fdiv_rn(ema_new, csn);
    if (d == 0) out[OFF_CS + k] = csn;
}

// ===========================================================================
extern "C" void kernel_launch(void* const* d_in, const int* in_sizes, int n_in,
                              void* d_out, int out_size) {
    const float* x       = (const float*)d_in[0];
    const float* emb_w   = (const float*)d_in[1];
    const float* ema_w   = (const float*)d_in[2];
    const float* ema_cs  = (const float*)d_in[3];
    float* out = (float*)d_out;

    cudaFuncSetAttribute(argmin_mma_kernel,
                         cudaFuncAttributeMaxDynamicSharedMemorySize, ARG_SMEM);

    zero_scratch_kernel<<<2048, 256>>>();
    e2_kernel<<<KK / 256, 256>>>(emb_w);
    argmin_mma_kernel<<<NN / 128, 256, ARG_SMEM>>>(x, emb_w);
    onehot_kernel<<<65536, 256>>>((float4*)out);
    scatter_kernel<<<(NN * DD) / 256, 256>>>(x);
    reduce_n_kernel<<<1, 1024>>>(ema_cs);
    finalize_kernel<<<(KK * DD) / 256, 256>>>(emb_w, ema_w, ema_cs, out);
}

// round 7
// speedup vs baseline: 1.3809x; 1.1225x over previous
#include <cuda_runtime.h>
#include <cstdint>
#include <cstddef>

// Problem constants
#define NN 32768
#define KK 8192
#define DD 64

// Output layout (tuple order, flattened)
#define OFF_CB  268435456ULL
#define OFF_CS  268959744ULL
#define OFF_EMA 268967936ULL
#define OFF_EMB 269492224ULL

#define DECAY 0.99f
#define OMD   0.01f
#define EPSV  1e-5f
#define KEPS  0.08192f   // K * EPS

// Scratch (device globals; no allocations allowed)
__device__ int   g_idx[NN];
__device__ float g_e2[KK];
__device__ float g_cnt[KK];
__device__ float g_dw[KK * DD];
__device__ float g_n;

// ===========================================================================
// helpers (sm_80-era PTX only: safe for the plain sm_103 ptxas target)
// ===========================================================================
static __device__ __forceinline__ uint32_t smem_u32(const void* p) {
    uint32_t a;
    asm("{ .reg .u64 t; cvta.to.shared.u64 t, %1; cvt.u32.u64 %0, t; }"
        : "=r"(a) : "l"(p));
    return a;
}

#define CP_ASYNC16(dst, src) \
    asm volatile("cp.async.cg.shared.global [%0], [%1], 16;" \
                 :: "r"(dst), "l"(src) : "memory")
#define CP_COMMIT() asm volatile("cp.async.commit_group;" ::: "memory")
#define CP_WAIT0()  asm volatile("cp.async.wait_group 0;"  ::: "memory")

// m16n8k8 row.col tf32 MMA, D += A*B (C aliases D)
static __device__ __forceinline__ void mma_tf32(float* d, const uint32_t* a,
                                                const uint32_t* b) {
    asm volatile(
        "mma.sync.aligned.m16n8k8.row.col.f32.tf32.tf32.f32 "
        "{%0,%1,%2,%3}, {%4,%5,%6,%7}, {%8,%9}, {%0,%1,%2,%3};"
        : "+f"(d[0]), "+f"(d[1]), "+f"(d[2]), "+f"(d[3])
        : "r"(a[0]), "r"(a[1]), "r"(a[2]), "r"(a[3]), "r"(b[0]), "r"(b[1]));
}

// exact hi split: keep top 10 explicit mantissa bits (tf32-representable)
#define TF32_MASK 0xFFFFE000u
static __device__ __forceinline__ uint32_t hi_bits(float v) {
    return __float_as_uint(v) & TF32_MASK;
}
static __device__ __forceinline__ uint32_t lo_bits(float v, uint32_t h) {
    return __float_as_uint(v - __uint_as_float(h)) & TF32_MASK;
}

// ===========================================================================
// 0) zero scratch
// ===========================================================================
__global__ void zero_scratch_kernel() {
    int i = blockIdx.x * 256 + threadIdx.x;
    if (i < KK * DD) g_dw[i] = 0.0f;
    if (i < KK)      g_cnt[i] = 0.0f;
}

// ===========================================================================
// 1) codebook squared norms
// ===========================================================================
__global__ void e2_kernel(const float* __restrict__ e) {
    int k = blockIdx.x * 256 + threadIdx.x;
    const float4* p = reinterpret_cast<const float4*>(e + (size_t)k * DD);
    float s = 0.0f;
#pragma unroll
    for (int i = 0; i < 16; ++i) {
        float4 v = p[i];
        s += v.x * v.x + v.y * v.y + v.z * v.z + v.w * v.w;
    }
    g_e2[k] = s;
}

// ===========================================================================
// 2) Tensor-core argmin via mma.sync (tf32), 3-term split precision.
//    CTA = 256 threads = 8 warps, 4(m) x 2(n).
//    CTA tile: 128 rows x all 8192 codewords (64 tiles of 128).
//    x pre-split (hi/lo tf32 planes) resident in SMEM; A frags via LDS per ks.
//    e raw f32 double-buffered via cp.async; split in regs with bit masks.
//    MMA order: ks-outer, 3 term-passes over 16 independent accumulators.
// ===========================================================================
#define SP   68                       // smem row stride in floats (64 + 4 pad)
#define SPB  (SP * 4)                 // 272 bytes
#define PLANE (128 * SPB)             // 34816 bytes per [128][SP] plane
#define X_HI 0
#define X_LO PLANE
#define EB0  (2 * PLANE)
#define EB1  (3 * PLANE)
#define CAND_OFF (4 * PLANE)
#define ARG_SMEM (CAND_OFF + 128 * 2 * 8)

__global__ __launch_bounds__(256, 1)
void argmin_mma_kernel(const float* __restrict__ x, const float* __restrict__ e) {
    extern __shared__ char sm[];
    const uint32_t sb = smem_u32(sm);
    const int tid = threadIdx.x;
    const int wid = tid >> 5;
    const int lane = tid & 31;
    const int g = lane >> 2;          // group id (0..7)
    const int r = lane & 3;           // thread-in-group (0..3)
    const int mw = wid & 3;           // m-warp -> rows mw*32..+31
    const int nw = wid >> 2;          // n-warp -> cols nw*64..+63
    const int row0 = blockIdx.x * 128;
    const int Cn = nw * 64;

    float* cand_d = reinterpret_cast<float*>(sm + CAND_OFF);
    int*   cand_i = reinterpret_cast<int*>(sm + CAND_OFF + 128 * 2 * 4);

    // ---- kick off e tile 0 prefetch (overlaps x staging) ----
    {
        const char* src = reinterpret_cast<const char*>(e);
#pragma unroll
        for (int i = 0; i < 8; ++i) {
            int ch = tid + 256 * i;
            int n = ch >> 4, kq = ch & 15;
            CP_ASYNC16(sb + EB0 + n * SPB + kq * 16, src + ch * 16);
        }
    }
    CP_COMMIT();

    // ---- stage x tile pre-split into X_HI / X_LO planes ----
    {
        const float4* xg = reinterpret_cast<const float4*>(x + (size_t)row0 * DD);
#pragma unroll
        for (int i = 0; i < 8; ++i) {
            int ch = tid + 256 * i;            // 0..2047 float4s
            int row = ch >> 4, q = ch & 15;
            float4 v = xg[ch];
            uint32_t hx = hi_bits(v.x), hy = hi_bits(v.y);
            uint32_t hz = hi_bits(v.z), hw = hi_bits(v.w);
            uint4 hv = make_uint4(hx, hy, hz, hw);
            uint4 lv = make_uint4(lo_bits(v.x, hx), lo_bits(v.y, hy),
                                  lo_bits(v.z, hz), lo_bits(v.w, hw));
            *reinterpret_cast<uint4*>(sm + X_HI + row * SPB + q * 16) = hv;
            *reinterpret_cast<uint4*>(sm + X_LO + row * SPB + q * 16) = lv;
        }
    }
    CP_WAIT0();
    __syncthreads();

    float best[4];
    int   bidx[4];
#pragma unroll
    for (int s = 0; s < 4; ++s) { best[s] = 3.402823466e38f; bidx[s] = 0; }

    const int NTILES = KK / 128;   // 64
    for (int t = 0; t < NTILES; ++t) {
        const char* bufc = sm + (((t & 1) == 0) ? EB0 : EB1);

        // prefetch tile t+1 into the other buffer
        if (t + 1 < NTILES) {
            const char* src = reinterpret_cast<const char*>(e + (size_t)(t + 1) * 128 * DD);
            const uint32_t bufn = sb + (((t & 1) == 0) ? EB1 : EB0);
#pragma unroll
            for (int i = 0; i < 8; ++i) {
                int ch = tid + 256 * i;
                int n = ch >> 4, kq = ch & 15;
                CP_ASYNC16(bufn + n * SPB + kq * 16, src + ch * 16);
            }
        }
        CP_COMMIT();

        // ---- compute: D[2][8][4], k=64 in 8 steps, 3 tf32 terms ----
        float D[2][8][4];
#pragma unroll
        for (int mf = 0; mf < 2; ++mf)
#pragma unroll
            for (int nb = 0; nb < 8; ++nb)
#pragma unroll
                for (int j = 0; j < 4; ++j) D[mf][nb][j] = 0.0f;

#pragma unroll
        for (int ks = 0; ks < 8; ++ks) {
            // A fragments for this ks (pre-split planes, conflict-free LDS)
            uint32_t ahi[2][4], alo[2][4];
#pragma unroll
            for (int mf = 0; mf < 2; ++mf) {
#pragma unroll
                for (int j = 0; j < 4; ++j) {
                    int row = mw * 32 + mf * 16 + g + ((j & 1) ? 8 : 0);
                    int col = ks * 8 + r + ((j & 2) ? 4 : 0);
                    ahi[mf][j] = *reinterpret_cast<const uint32_t*>(
                        sm + X_HI + row * SPB + col * 4);
                    alo[mf][j] = *reinterpret_cast<const uint32_t*>(
                        sm + X_LO + row * SPB + col * 4);
                }
            }
            // B fragments for all 8 nb (raw f32 -> mask split in regs)
            uint32_t bhi[8][2], blo[8][2];
#pragma unroll
            for (int nb = 0; nb < 8; ++nb) {
                const char* np = bufc + (size_t)(Cn + nb * 8 + g) * SPB;
                float v0 = *reinterpret_cast<const float*>(np + (ks * 8 + r) * 4);
                float v1 = *reinterpret_cast<const float*>(np + (ks * 8 + r + 4) * 4);
                bhi[nb][0] = hi_bits(v0);
                bhi[nb][1] = hi_bits(v1);
                blo[nb][0] = lo_bits(v0, bhi[nb][0]);
                blo[nb][1] = lo_bits(v1, bhi[nb][1]);
            }
            // 3 term-passes, 16 independent accumulators each
#pragma unroll
            for (int nb = 0; nb < 8; ++nb) {
                mma_tf32(D[0][nb], ahi[0], bhi[nb]);
                mma_tf32(D[1][nb], ahi[1], bhi[nb]);
            }
#pragma unroll
            for (int nb = 0; nb < 8; ++nb) {
                mma_tf32(D[0][nb], alo[0], bhi[nb]);
                mma_tf32(D[1][nb], alo[1], bhi[nb]);
            }
#pragma unroll
            for (int nb = 0; nb < 8; ++nb) {
                mma_tf32(D[0][nb], ahi[0], blo[nb]);
                mma_tf32(D[1][nb], ahi[1], blo[nb]);
            }
        }

        // ---- epilogue: distances + running argmin ----
        // frag c-layout: c0(row g, col 2r), c1(row g, col 2r+1),
        //                c2(row g+8, col 2r), c3(row g+8, col 2r+1)
#pragma unroll
        for (int nb = 0; nb < 8; ++nb) {
            int col = t * 128 + Cn + nb * 8 + r * 2;
            float2 q = *reinterpret_cast<const float2*>(&g_e2[col]);
#pragma unroll
            for (int mf = 0; mf < 2; ++mf) {
                float d0 = fmaf(-2.0f, D[mf][nb][0], q.x);
                float d1 = fmaf(-2.0f, D[mf][nb][1], q.y);
                float d2 = fmaf(-2.0f, D[mf][nb][2], q.x);
                float d3 = fmaf(-2.0f, D[mf][nb][3], q.y);
                int s0 = mf * 2, s1 = mf * 2 + 1;
                if (d0 < best[s0]) { best[s0] = d0; bidx[s0] = col; }
                if (d1 < best[s0]) { best[s0] = d1; bidx[s0] = col + 1; }
                if (d2 < best[s1]) { best[s1] = d2; bidx[s1] = col; }
                if (d3 < best[s1]) { best[s1] = d3; bidx[s1] = col + 1; }
            }
        }

        CP_WAIT0();
        __syncthreads();
    }

    // ---- reduce across the 4 lanes of each quad (same rows, diff cols) ----
#pragma unroll
    for (int m = 1; m <= 2; m <<= 1) {
#pragma unroll
        for (int s = 0; s < 4; ++s) {
            float ob = __shfl_xor_sync(0xffffffffu, best[s], m);
            int   oi = __shfl_xor_sync(0xffffffffu, bidx[s], m);
            if (ob < best[s] || (ob == best[s] && oi < bidx[s])) {
                best[s] = ob; bidx[s] = oi;
            }
        }
    }
    if (r == 0) {
#pragma unroll
        for (int s = 0; s < 4; ++s) {
            int row = mw * 32 + g + s * 8;   // s0:g s1:g+8 s2:g+16 s3:g+24
            cand_d[nw * 128 + row] = best[s];
            cand_i[nw * 128 + row] = bidx[s];
        }
    }
    __syncthreads();
    if (tid < 128) {
        float d0 = cand_d[tid], d1 = cand_d[128 + tid];
        int   i0 = cand_i[tid], i1 = cand_i[128 + tid];
        int win = (d1 < d0 || (d1 == d0 && i1 < i0)) ? i1 : i0;
        g_idx[row0 + tid] = win;
    }
}

// ===========================================================================
// 3) encodings: fused zero + one-hot, 16B/thread plain stores (best measured)
// ===========================================================================
__global__ void onehot_kernel(float4* __restrict__ out) {
    int i = blockIdx.x * 256 + threadIdx.x;     // 67,108,864 float4s
    int row = i >> 11;                          // K/4 = 2048 float4 per row
    int c4  = i & 2047;
    int idx = __ldg(&g_idx[row]);
    float4 v = make_float4(0.0f, 0.0f, 0.0f, 0.0f);
    if ((idx >> 2) == c4) {
        reinterpret_cast<float*>(&v)[idx & 3] = 1.0f;
    }
    out[i] = v;
}

// ===========================================================================
// 4) dw scatter + counts
// ===========================================================================
__global__ void scatter_kernel(const float* __restrict__ x) {
    int gid = blockIdx.x * 256 + threadIdx.x;
    int n = gid >> 6, d = gid & 63;
    int k = g_idx[n];
    atomicAdd(&g_dw[(size_t)k * DD + d], x[gid]);
    if (d == 0) atomicAdd(&g_cnt[k], 1.0f);
}

// ===========================================================================
// 5) n = sum(cluster_size_pre)
// ===========================================================================
__global__ void reduce_n_kernel(const float* __restrict__ ema_cs) {
    __shared__ float sh[1024];
    int t = threadIdx.x;
    float s = 0.0f;
    for (int k = t; k < KK; k += 1024) {
        float cs = __fadd_rn(__fmul_rn(ema_cs[k], DECAY), __fmul_rn(OMD, g_cnt[k]));
        s += cs;
    }
    sh[t] = s;
    __syncthreads();
    for (int m = 512; m > 0; m >>= 1) {
        if (t < m) sh[t] += sh[t + m];
        __syncthreads();
    }
    if (t == 0) g_n = sh[0];
}

// ===========================================================================
// 6) finalize
// ===========================================================================
__global__ void finalize_kernel(const float* __restrict__ emb_w,
                                const float* __restrict__ ema_w,
                                const float* __restrict__ ema_cs,
                                float* __restrict__ out) {
    int gid = blockIdx.x * 256 + threadIdx.x;
    int k = gid >> 6, d = gid & 63;
    float nsum = g_n;
    float cs  = __fadd_rn(__fmul_rn(ema_cs[k], DECAY), __fmul_rn(OMD, g_cnt[k]));
    float csn = __fmul_rn(__fdiv_rn(__fadd_rn(cs, EPSV), __fadd_rn(nsum, KEPS)), nsum);
    float ema_new = __fadd_rn(__fmul_rn(ema_w[gid], DECAY), __fmul_rn(OMD, g_dw[gid]));
    out[OFF_CB  + gid] = emb_w[gid];
    out[OFF_EMA + gid] = ema_new;
    out[OFF_EMB + gid] = __fdiv_rn(ema_new, csn);
    if (d == 0) out[OFF_CS + k] = csn;
}

// ===========================================================================
extern "C" void kernel_launch(void* const* d_in, const int* in_sizes, int n_in,
                              void* d_out, int out_size) {
    const float* x       = (const float*)d_in[0];
    const float* emb_w   = (const float*)d_in[1];
    const float* ema_w   = (const float*)d_in[2];
    const float* ema_cs  = (const float*)d_in[3];
    float* out = (float*)d_out;

    cudaFuncSetAttribute(argmin_mma_kernel,
                         cudaFuncAttributeMaxDynamicSharedMemorySize, ARG_SMEM);

    zero_scratch_kernel<<<2048, 256>>>();
    e2_kernel<<<KK / 256, 256>>>(emb_w);
    argmin_mma_kernel<<<NN / 128, 256, ARG_SMEM>>>(x, emb_w);
    onehot_kernel<<<(NN * (KK / 4)) / 256, 256>>>((float4*)out);
    scatter_kernel<<<(NN * DD) / 256, 256>>>(x);
    reduce_n_kernel<<<1, 1024>>>(ema_cs);
    finalize_kernel<<<(KK * DD) / 256, 256>>>(emb_w, ema_w, ema_cs, out);
}

// round 9
// speedup vs baseline: 1.8383x; 1.3312x over previous
#include <cuda_runtime.h>
#include <cstdint>
#include <cstddef>

// Problem constants
#define NN 32768
#define KK 8192
#define DD 64

// Output layout (tuple order, flattened)
#define OFF_CB  268435456ULL
#define OFF_CS  268959744ULL
#define OFF_EMA 268967936ULL
#define OFF_EMB 269492224ULL

#define DECAY 0.99f
#define OMD   0.01f
#define EPSV  1e-5f
#define KEPS  0.08192f   // K * EPS

// Scratch (device globals; no allocations allowed)
__device__ int   g_idx[NN];
__device__ float g_e2[KK];
__device__ float g_cnt[KK];
__device__ float g_dw[KK * DD];
__device__ float g_n;

// ===========================================================================
// helpers (sm_80-era PTX only: safe for the plain sm_103 ptxas target)
// ===========================================================================
static __device__ __forceinline__ uint32_t smem_u32(const void* p) {
    uint32_t a;
    asm("{ .reg .u64 t; cvta.to.shared.u64 t, %1; cvt.u32.u64 %0, t; }"
        : "=r"(a) : "l"(p));
    return a;
}

#define CP_ASYNC16(dst, src) \
    asm volatile("cp.async.cg.shared.global [%0], [%1], 16;" \
                 :: "r"(dst), "l"(src) : "memory")
#define CP_COMMIT() asm volatile("cp.async.commit_group;" ::: "memory")
#define CP_WAIT0()  asm volatile("cp.async.wait_group 0;"  ::: "memory")

// m16n8k8 row.col tf32 MMA, D += A*B (C aliases D)
static __device__ __forceinline__ void mma_tf32(float* d, const uint32_t* a,
                                                const uint32_t* b) {
    asm volatile(
        "mma.sync.aligned.m16n8k8.row.col.f32.tf32.tf32.f32 "
        "{%0,%1,%2,%3}, {%4,%5,%6,%7}, {%8,%9}, {%0,%1,%2,%3};"
        : "+f"(d[0]), "+f"(d[1]), "+f"(d[2]), "+f"(d[3])
        : "r"(a[0]), "r"(a[1]), "r"(a[2]), "r"(a[3]), "r"(b[0]), "r"(b[1]));
}

// exact hi split: keep top 10 explicit mantissa bits (tf32-representable)
#define TF32_MASK 0xFFFFE000u
static __device__ __forceinline__ uint32_t hi_bits(float v) {
    return __float_as_uint(v) & TF32_MASK;
}
static __device__ __forceinline__ uint32_t lo_bits(float v, uint32_t h) {
    return __float_as_uint(v - __uint_as_float(h)) & TF32_MASK;
}

// ===========================================================================
// 0) zero scratch
// ===========================================================================
__global__ void zero_scratch_kernel() {
    int i = blockIdx.x * 256 + threadIdx.x;
    if (i < KK * DD) g_dw[i] = 0.0f;
    if (i < KK)      g_cnt[i] = 0.0f;
}

// ===========================================================================
// 1) codebook squared norms
// ===========================================================================
__global__ void e2_kernel(const float* __restrict__ e) {
    int k = blockIdx.x * 256 + threadIdx.x;
    const float4* p = reinterpret_cast<const float4*>(e + (size_t)k * DD);
    float s = 0.0f;
#pragma unroll
    for (int i = 0; i < 16; ++i) {
        float4 v = p[i];
        s += v.x * v.x + v.y * v.y + v.z * v.z + v.w * v.w;
    }
    g_e2[k] = s;
}

// ===========================================================================
// 2) Fused tensor-core argmin + encodings writer.
//    CTA = 256 threads = 8 warps, 4(m) x 2(n); 128 rows per CTA,
//    64 codeword tiles of 128.  3-term tf32 split (validated exact vs ref).
//    NEW: the one-hot zero stripe (128 rows x 8192 cols, all-zero except one
//    element/row) is streamed progressively inside the tile loop (64 KB/iter,
//    __stcs), overlapping DRAM writes with tensor compute.  The single 1.0
//    per row is written after the final argmin reduction (same CTA; ordering
//    via __syncthreads).
// ===========================================================================
#define SP   68                       // smem row stride in floats (64 + 4 pad)
#define SPB  (SP * 4)                 // 272 bytes
#define PLANE (128 * SPB)             // 34816 bytes per [128][SP] plane
#define X_HI 0
#define X_LO PLANE
#define EB0  (2 * PLANE)
#define EB1  (3 * PLANE)
#define CAND_OFF (4 * PLANE)
#define ARG_SMEM (CAND_OFF + 128 * 2 * 8)

__global__ __launch_bounds__(256, 1)
void argmin_mma_kernel(const float* __restrict__ x, const float* __restrict__ e,
                       float* __restrict__ out) {
    extern __shared__ char sm[];
    const uint32_t sb = smem_u32(sm);
    const int tid = threadIdx.x;
    const int wid = tid >> 5;
    const int lane = tid & 31;
    const int g = lane >> 2;          // group id (0..7)
    const int r = lane & 3;           // thread-in-group (0..3)
    const int mw = wid & 3;           // m-warp -> rows mw*32..+31
    const int nw = wid >> 2;          // n-warp -> cols nw*64..+63
    const int row0 = blockIdx.x * 128;
    const int Cn = nw * 64;

    float* cand_d = reinterpret_cast<float*>(sm + CAND_OFF);
    int*   cand_i = reinterpret_cast<int*>(sm + CAND_OFF + 128 * 2 * 4);

    // ---- kick off e tile 0 prefetch (overlaps x staging) ----
    {
        const char* src = reinterpret_cast<const char*>(e);
#pragma unroll
        for (int i = 0; i < 8; ++i) {
            int ch = tid + 256 * i;
            int n = ch >> 4, kq = ch & 15;
            CP_ASYNC16(sb + EB0 + n * SPB + kq * 16, src + ch * 16);
        }
    }
    CP_COMMIT();

    // ---- stage x tile pre-split into X_HI / X_LO planes ----
    {
        const float4* xg = reinterpret_cast<const float4*>(x + (size_t)row0 * DD);
#pragma unroll
        for (int i = 0; i < 8; ++i) {
            int ch = tid + 256 * i;            // 0..2047 float4s
            int row = ch >> 4, q = ch & 15;
            float4 v = xg[ch];
            uint32_t hx = hi_bits(v.x), hy = hi_bits(v.y);
            uint32_t hz = hi_bits(v.z), hw = hi_bits(v.w);
            uint4 hv = make_uint4(hx, hy, hz, hw);
            uint4 lv = make_uint4(lo_bits(v.x, hx), lo_bits(v.y, hy),
                                  lo_bits(v.z, hz), lo_bits(v.w, hw));
            *reinterpret_cast<uint4*>(sm + X_HI + row * SPB + q * 16) = hv;
            *reinterpret_cast<uint4*>(sm + X_LO + row * SPB + q * 16) = lv;
        }
    }
    CP_WAIT0();
    __syncthreads();

    float best[4];
    int   bidx[4];
#pragma unroll
    for (int s = 0; s < 4; ++s) { best[s] = 3.402823466e38f; bidx[s] = 0; }

    // encodings base for this CTA (float4 granularity; row stride 2048 f4)
    float4* enc = reinterpret_cast<float4*>(out) + (size_t)row0 * 2048;
    const float4 fz = make_float4(0.0f, 0.0f, 0.0f, 0.0f);

    const int NTILES = KK / 128;   // 64
    for (int t = 0; t < NTILES; ++t) {
        const char* bufc = sm + (((t & 1) == 0) ? EB0 : EB1);

        // prefetch tile t+1 into the other buffer
        if (t + 1 < NTILES) {
            const char* src = reinterpret_cast<const char*>(e + (size_t)(t + 1) * 128 * DD);
            const uint32_t bufn = sb + (((t & 1) == 0) ? EB1 : EB0);
#pragma unroll
            for (int i = 0; i < 8; ++i) {
                int ch = tid + 256 * i;
                int n = ch >> 4, kq = ch & 15;
                CP_ASYNC16(bufn + n * SPB + kq * 16, src + ch * 16);
            }
        }
        CP_COMMIT();

        // ---- stream the zero stripe for this tile's 128 columns ----
        // stripe: rows [0,128) x float4-cols [t*32, t*32+32); 4096 float4s
        {
            float4* zb = enc + t * 32;
#pragma unroll
            for (int j = 0; j < 16; ++j) {
                int i = tid + 256 * j;         // 0..4095
                int row = i >> 5, c4 = i & 31; // warp -> one contiguous 512B run
                __stcs(&zb[(size_t)row * 2048 + c4], fz);
            }
        }

        // ---- compute: D[2][8][4], k=64 in 8 steps, 3 tf32 terms ----
        float D[2][8][4];
#pragma unroll
        for (int mf = 0; mf < 2; ++mf)
#pragma unroll
            for (int nb = 0; nb < 8; ++nb)
#pragma unroll
                for (int j = 0; j < 4; ++j) D[mf][nb][j] = 0.0f;

#pragma unroll
        for (int ks = 0; ks < 8; ++ks) {
            // A fragments for this ks (pre-split planes, conflict-free LDS)
            uint32_t ahi[2][4], alo[2][4];
#pragma unroll
            for (int mf = 0; mf < 2; ++mf) {
#pragma unroll
                for (int j = 0; j < 4; ++j) {
                    int row = mw * 32 + mf * 16 + g + ((j & 1) ? 8 : 0);
                    int col = ks * 8 + r + ((j & 2) ? 4 : 0);
                    ahi[mf][j] = *reinterpret_cast<const uint32_t*>(
                        sm + X_HI + row * SPB + col * 4);
                    alo[mf][j] = *reinterpret_cast<const uint32_t*>(
                        sm + X_LO + row * SPB + col * 4);
                }
            }
            // B fragments for all 8 nb (raw f32 -> mask split in regs)
            uint32_t bhi[8][2], blo[8][2];
#pragma unroll
            for (int nb = 0; nb < 8; ++nb) {
                const char* np = bufc + (size_t)(Cn + nb * 8 + g) * SPB;
                float v0 = *reinterpret_cast<const float*>(np + (ks * 8 + r) * 4);
                float v1 = *reinterpret_cast<const float*>(np + (ks * 8 + r + 4) * 4);
                bhi[nb][0] = hi_bits(v0);
                bhi[nb][1] = hi_bits(v1);
                blo[nb][0] = lo_bits(v0, bhi[nb][0]);
                blo[nb][1] = lo_bits(v1, bhi[nb][1]);
            }
            // 3 term-passes, 16 independent accumulators each
#pragma unroll
            for (int nb = 0; nb < 8; ++nb) {
                mma_tf32(D[0][nb], ahi[0], bhi[nb]);
                mma_tf32(D[1][nb], ahi[1], bhi[nb]);
            }
#pragma unroll
            for (int nb = 0; nb < 8; ++nb) {
                mma_tf32(D[0][nb], alo[0], bhi[nb]);
                mma_tf32(D[1][nb], alo[1], bhi[nb]);
            }
#pragma unroll
            for (int nb = 0; nb < 8; ++nb) {
                mma_tf32(D[0][nb], ahi[0], blo[nb]);
                mma_tf32(D[1][nb], ahi[1], blo[nb]);
            }
        }

        // ---- epilogue: distances + running argmin ----
        // frag c-layout: c0(row g, col 2r), c1(row g, col 2r+1),
        //                c2(row g+8, col 2r), c3(row g+8, col 2r+1)
#pragma unroll
        for (int nb = 0; nb < 8; ++nb) {
            int col = t * 128 + Cn + nb * 8 + r * 2;
            float2 q = *reinterpret_cast<const float2*>(&g_e2[col]);
#pragma unroll
            for (int mf = 0; mf < 2; ++mf) {
                float d0 = fmaf(-2.0f, D[mf][nb][0], q.x);
                float d1 = fmaf(-2.0f, D[mf][nb][1], q.y);
                float d2 = fmaf(-2.0f, D[mf][nb][2], q.x);
                float d3 = fmaf(-2.0f, D[mf][nb][3], q.y);
                int s0 = mf * 2, s1 = mf * 2 + 1;
                if (d0 < best[s0]) { best[s0] = d0; bidx[s0] = col; }
                if (d1 < best[s0]) { best[s0] = d1; bidx[s0] = col + 1; }
                if (d2 < best[s1]) { best[s1] = d2; bidx[s1] = col; }
                if (d3 < best[s1]) { best[s1] = d3; bidx[s1] = col + 1; }
            }
        }

        CP_WAIT0();
        __syncthreads();
    }

    // ---- reduce across the 4 lanes of each quad (same rows, diff cols) ----
#pragma unroll
    for (int m = 1; m <= 2; m <<= 1) {
#pragma unroll
        for (int s = 0; s < 4; ++s) {
            float ob = __shfl_xor_sync(0xffffffffu, best[s], m);
            int   oi = __shfl_xor_sync(0xffffffffu, bidx[s], m);
            if (ob < best[s] || (ob == best[s] && oi < bidx[s])) {
                best[s] = ob; bidx[s] = oi;
            }
        }
    }
    if (r == 0) {
#pragma unroll
        for (int s = 0; s < 4; ++s) {
            int row = mw * 32 + g + s * 8;   // s0:g s1:g+8 s2:g+16 s3:g+24
            cand_d[nw * 128 + row] = best[s];
            cand_i[nw * 128 + row] = bidx[s];
        }
    }
    __syncthreads();   // also orders the zero stores before the 1.0 stores
    if (tid < 128) {
        float d0 = cand_d[tid], d1 = cand_d[128 + tid];
        int   i0 = cand_i[tid], i1 = cand_i[128 + tid];
        int win = (d1 < d0 || (d1 == d0 && i1 < i0)) ? i1 : i0;
        g_idx[row0 + tid] = win;
        out[(size_t)(row0 + tid) * KK + win] = 1.0f;   // the one-hot 1
    }
}

// ===========================================================================
// 3) dw scatter + counts
// ===========================================================================
__global__ void scatter_kernel(const float* __restrict__ x) {
    int gid = blockIdx.x * 256 + threadIdx.x;
    int n = gid >> 6, d = gid & 63;
    int k = g_idx[n];
    atomicAdd(&g_dw[(size_t)k * DD + d], x[gid]);
    if (d == 0) atomicAdd(&g_cnt[k], 1.0f);
}

// ===========================================================================
// 4) n = sum(cluster_size_pre)
// ===========================================================================
__global__ void reduce_n_kernel(const float* __restrict__ ema_cs) {
    __shared__ float sh[1024];
    int t = threadIdx.x;
    float s = 0.0f;
    for (int k = t; k < KK; k += 1024) {
        float cs = __fadd_rn(__fmul_rn(ema_cs[k], DECAY), __fmul_rn(OMD, g_cnt[k]));
        s += cs;
    }
    sh[t] = s;
    __syncthreads();
    for (int m = 512; m > 0; m >>= 1) {
        if (t < m) sh[t] += sh[t + m];
        __syncthreads();
    }
    if (t == 0) g_n = sh[0];
}

// ===========================================================================
// 5) finalize
// ===========================================================================
__global__ void finalize_kernel(const float* __restrict__ emb_w,
                                const float* __restrict__ ema_w,
                                const float* __restrict__ ema_cs,
                                float* __restrict__ out) {
    int gid = blockIdx.x * 256 + threadIdx.x;
    int k = gid >> 6, d = gid & 63;
    float nsum = g_n;
    float cs  = __fadd_rn(__fmul_rn(ema_cs[k], DECAY), __fmul_rn(OMD, g_cnt[k]));
    float csn = __fmul_rn(__fdiv_rn(__fadd_rn(cs, EPSV), __fadd_rn(nsum, KEPS)), nsum);
    float ema_new = __fadd_rn(__fmul_rn(ema_w[gid], DECAY), __fmul_rn(OMD, g_dw[gid]));
    out[OFF_CB  + gid] = emb_w[gid];
    out[OFF_EMA + gid] = ema_new;
    out[OFF_EMB + gid] = __fdiv_rn(ema_new, csn);
    if (d == 0) out[OFF_CS + k] = csn;
}

// ===========================================================================
extern "C" void kernel_launch(void* const* d_in, const int* in_sizes, int n_in,
                              void* d_out, int out_size) {
    const float* x       = (const float*)d_in[0];
    const float* emb_w   = (const float*)d_in[1];
    const float* ema_w   = (const float*)d_in[2];
    const float* ema_cs  = (const float*)d_in[3];
    float* out = (float*)d_out;

    cudaFuncSetAttribute(argmin_mma_kernel,
                         cudaFuncAttributeMaxDynamicSharedMemorySize, ARG_SMEM);

    zero_scratch_kernel<<<2048, 256>>>();
    e2_kernel<<<KK / 256, 256>>>(emb_w);
    argmin_mma_kernel<<<NN / 128, 256, ARG_SMEM>>>(x, emb_w, out);
    scatter_kernel<<<(NN * DD) / 256, 256>>>(x);
    reduce_n_kernel<<<1, 1024>>>(ema_cs);
    finalize_kernel<<<(KK * DD) / 256, 256>>>(emb_w, ema_w, ema_cs, out);
}